// round 3
// baseline (speedup 1.0000x reference)
#include <cuda_runtime.h>

// SpectralConv1d: out[row,o,k,:] = sum_i complex( x[row,i,k,:] * w[o,i,k,:] )
// rows = 16384, i = o = 32, k = 64, complex = 2 fp32.
//
// Round 3: pure-streaming f32x2 kernel.
//  - complex MAC via dual accumulators, x operand = raw (xr,xi) 8B gmem value:
//      accA += (xr,xi)*(wr,wr)   -> (sum xr*wr, sum xi*wr)
//      accB += (xr,xi)*(wi,wi)   -> (sum xr*wi, sum xi*wi)
//      R = accA.lo - accB.hi ;  I = accA.hi + accB.lo
//  - weights in smem as (wr,wr,wi,wi) float4, layout [k][i][o^k] (swizzled)
//  - x via LDG.64 broadcast (L1-resident across the 8 k-warps of the CTA)
//  - no x smem, no per-tile syncs; 16 warps free-run after weight load
//  - warp = 16 rows x 32 o x 1 k ; lane tile = 4 rows x 4 o (64 acc regs)

#define THREADS 512
#define KT      8       // k per CTA
#define RB      32      // rows per block (2 warp row-halves of 16)
#define BLOCKS  4       // row blocks per CTA -> 128 rows
#define SW_F4   8192    // 8k * 32i * 32o float4
#define SMEM_BYTES (SW_F4 * 16)   // 131072

__device__ __forceinline__ void ffma2(unsigned long long &d,
                                      unsigned long long a,
                                      unsigned long long b) {
    asm("fma.rn.f32x2 %0, %1, %2, %0;" : "+l"(d) : "l"(a), "l"(b));
}

__device__ __forceinline__ float2 cmerge(unsigned long long a, unsigned long long b) {
    float ax, ay, bx, by;
    asm("mov.b64 {%0,%1}, %2;" : "=f"(ax), "=f"(ay) : "l"(a));
    asm("mov.b64 {%0,%1}, %2;" : "=f"(bx), "=f"(by) : "l"(b));
    return make_float2(ax - by, ay + bx);
}

__global__ void __launch_bounds__(THREADS, 1)
spectral_r3_kernel(const float* __restrict__ X,
                   const float* __restrict__ W,
                   float* __restrict__ O)
{
    extern __shared__ float4 sW4[];
    const ulonglong2* sWu = reinterpret_cast<const ulonglong2*>(sW4);

    const int tid  = threadIdx.x;
    const int lane = tid & 31;
    const int warp = tid >> 5;
    const int kl   = warp & 7;          // warp's local k
    const int rh   = warp >> 3;         // row half (0/1) within 32-row block
    const int og   = lane & 7;          // o group: o = og + 8*oi
    const int rp   = lane >> 3;         // row group: rows rp*4 .. rp*4+3 (of 16)
    const int kg   = blockIdx.x * KT;
    const long rowBase = (long)blockIdx.y * (RB * BLOCKS);

    // ---- weights -> smem as (wr, wr, wi, wi), layout [kw][i][o ^ kw] ----
    // Gmem-coalesced (kw fastest); STS.128 hits the 4-wavefront floor;
    // compute-side LDS.128 over og is 8 consecutive (permuted) slots = 1 wf.
    #pragma unroll
    for (int it = 0; it < 16; ++it) {
        int idx = tid + it * THREADS;
        int kw = idx & 7, i = (idx >> 3) & 31, o = idx >> 8;
        float2 wv = *reinterpret_cast<const float2*>(
            W + (size_t)o * 4096 + i * 128 + (size_t)(kg + kw) * 2);
        sW4[kw * 1024 + i * 32 + (o ^ kw)] = make_float4(wv.x, wv.x, wv.y, wv.y);
    }
    __syncthreads();

    const int row0 = rh * 16 + rp * 4;      // lane's first row within block
    // per-lane w slot indices (constant): kl*1024 + i*32 + ((og + 8*oi) ^ kl)
    int wslot[4];
    #pragma unroll
    for (int oi = 0; oi < 4; ++oi)
        wslot[oi] = kl * 1024 + ((og + 8 * oi) ^ kl);

    for (int b = 0; b < BLOCKS; ++b) {
        const long rbase = rowBase + (long)b * RB;
        const float* xp = X + (rbase + row0) * 4096 + (size_t)(kg + kl) * 2;

        unsigned long long accA[4][4], accB[4][4];
        #pragma unroll
        for (int r = 0; r < 4; ++r)
            #pragma unroll
            for (int oi = 0; oi < 4; ++oi) { accA[r][oi] = 0ULL; accB[r][oi] = 0ULL; }

        #pragma unroll 8
        for (int i = 0; i < 32; ++i) {
            unsigned long long xv[4];
            #pragma unroll
            for (int r = 0; r < 4; ++r)
                xv[r] = *reinterpret_cast<const unsigned long long*>(
                            xp + (size_t)r * 4096 + i * 128);
            #pragma unroll
            for (int oi = 0; oi < 4; ++oi) {
                ulonglong2 wv = sWu[wslot[oi] + i * 32];   // (wr,wr)|(wi,wi)
                #pragma unroll
                for (int r = 0; r < 4; ++r) {
                    ffma2(accA[r][oi], xv[r], wv.x);
                    ffma2(accB[r][oi], xv[r], wv.y);
                }
            }
        }

        // ---- epilogue: combine + direct store (L2 merges the 8B pieces) ----
        #pragma unroll
        for (int r = 0; r < 4; ++r) {
            float* op = O + (rbase + row0 + r) * 4096 + (size_t)(kg + kl) * 2;
            #pragma unroll
            for (int oi = 0; oi < 4; ++oi) {
                int o = og + 8 * oi;
                *reinterpret_cast<float2*>(op + (size_t)o * 128) =
                    cmerge(accA[r][oi], accB[r][oi]);
            }
        }
    }
}

extern "C" void kernel_launch(void* const* d_in, const int* in_sizes, int n_in,
                              void* d_out, int out_size)
{
    const float* x = (const float*)d_in[0];   // (8,2048,32,64,2) fp32
    const float* w = (const float*)d_in[1];   // (32,32,64,2) fp32
    float* out = (float*)d_out;               // (8,2048,32,64,2) fp32

    cudaFuncSetAttribute(spectral_r3_kernel,
                         cudaFuncAttributeMaxDynamicSharedMemorySize, SMEM_BYTES);
    dim3 grid(64 / KT, 16384 / (RB * BLOCKS));   // (8, 128); k fastest => L2 x-reuse
    spectral_r3_kernel<<<grid, THREADS, SMEM_BYTES>>>(x, w, out);
}

// round 4
// speedup vs baseline: 1.0190x; 1.0190x over previous
#include <cuda_runtime.h>

// SpectralConv1d: out[row,o,k,:] = sum_i complex( x[row,i,k,:] * w[o,i,k,:] )
// rows = 16384, i = o = 32, k = 64, complex = 2 fp32.
//
// Round 4: smem-fed dual-accumulator f32x2 kernel.
//   accA += (xr,xi)*(wr,wr) ; accB += (xr,xi)*(wi,wi)
//   R = accA.lo - accB.hi   ; I = accA.hi + accB.lo
//  - w in smem as (wr,wr,wi,wi) float4 [k][i][o]      (128 KB)
//  - x in smem raw float2 [row][i][slot], slot = k ^ ((row>>2&3)*2)  (64 KB)
//    filled by cp.async 16B (register-free), overlapped with the store phase
//  - 16 warps = 8 k x 2 row-halves; lane tile = 4 rows x 4 o (dual acc)
//  - direct float2 stores (adjacent k covered by sibling warps -> L2 merge)

#define THREADS 512
#define KT      8
#define RT      32                    // rows per tile
#define TILES   4                     // 128 rows per CTA
#define SW_F4   8192                  // 8k*32i*32o float4
#define SX_BYTES (RT * 2048)          // 32 rows * 32 i * 8 slots * 8B
#define SMEM_BYTES (SW_F4 * 16 + SX_BYTES)   // 131072 + 65536 = 196608

__device__ __forceinline__ void ffma2(unsigned long long &d,
                                      unsigned long long a,
                                      unsigned long long b) {
    asm("fma.rn.f32x2 %0, %1, %2, %0;" : "+l"(d) : "l"(a), "l"(b));
}
__device__ __forceinline__ float2 cmerge(unsigned long long a, unsigned long long b) {
    float ax, ay, bx, by;
    asm("mov.b64 {%0,%1}, %2;" : "=f"(ax), "=f"(ay) : "l"(a));
    asm("mov.b64 {%0,%1}, %2;" : "=f"(bx), "=f"(by) : "l"(b));
    return make_float2(ax - by, ay + bx);
}
__device__ __forceinline__ unsigned smem_u32(const void* p) {
    unsigned a;
    asm("{ .reg .u64 t; cvta.to.shared.u64 t, %1; cvt.u32.u64 %0, t; }"
        : "=r"(a) : "l"(p));
    return a;
}
__device__ __forceinline__ void cp_async16(unsigned dst, const void* src) {
    asm volatile("cp.async.ca.shared.global [%0], [%1], 16;\n"
                 :: "r"(dst), "l"(src));
}
__device__ __forceinline__ void cp_commit() {
    asm volatile("cp.async.commit_group;\n");
}
__device__ __forceinline__ void cp_wait0() {
    asm volatile("cp.async.wait_group 0;\n");
}

__global__ void __launch_bounds__(THREADS, 1)
spectral_r4_kernel(const float* __restrict__ X,
                   const float* __restrict__ W,
                   float* __restrict__ O)
{
    extern __shared__ float4 sW4[];                       // [k][i][o]
    char* sXc = reinterpret_cast<char*>(sW4 + SW_F4);     // x tile bytes
    const ulonglong2* sWu = reinterpret_cast<const ulonglong2*>(sW4);
    const unsigned sXbase = smem_u32(sXc);

    const int tid  = threadIdx.x;
    const int lane = tid & 31;
    const int warp = tid >> 5;
    const int kl   = warp & 7;           // warp's local k
    const int rh   = warp >> 3;          // row half of the 32-row tile
    const int og   = lane & 7;           // o = og + 8*oi
    const int rp   = lane >> 3;          // rows rp*4 .. rp*4+3 (within half)
    const int kg   = blockIdx.x * KT;
    const long rowBase = (long)blockIdx.y * (RT * TILES);

    // ---- weights -> smem (wr,wr,wi,wi) [k][i][o] ----
    #pragma unroll
    for (int it = 0; it < 16; ++it) {
        int idx = tid + it * THREADS;
        int o = idx & 31, i = (idx >> 5) & 31, kw = idx >> 10;
        float2 wv = *reinterpret_cast<const float2*>(
            W + (size_t)o * 4096 + i * 128 + (size_t)(kg + kw) * 2);
        sW4[kw * 1024 + i * 32 + o] = make_float4(wv.x, wv.x, wv.y, wv.y);
    }

    // ---- fill tile 0 via cp.async ----
    // chunk idx: k2 = idx&3 (pair of k), i = (idx>>2)&31, row = idx>>7
    // smem: row*2048 + i*64 + ((2*k2) ^ s)*8, s = ((row>>2)&3)*2  (even -> 16B intact)
    {
        #pragma unroll
        for (int it = 0; it < 8; ++it) {
            int idx = tid + it * THREADS;
            int k2 = idx & 3, i = (idx >> 2) & 31, row = idx >> 7;
            int s = ((row >> 2) & 3) << 1;
            const float* src = X + (rowBase + row) * 4096 + i * 128
                                 + (size_t)(kg + k2 * 2) * 2;
            cp_async16(sXbase + row * 2048 + i * 64 + (((2 * k2) ^ s) << 3), src);
        }
        cp_commit();
    }
    cp_wait0();
    __syncthreads();

    const int row0   = rh * 16 + rp * 4;            // lane's first row in tile
    const int xslot  = kl ^ (rp << 1);              // swizzled slot for this lane
    const unsigned xb = sXbase + row0 * 2048 + (xslot << 3);
    int wslot[4];
    #pragma unroll
    for (int oi = 0; oi < 4; ++oi)
        wslot[oi] = kl * 1024 + og + 8 * oi;

    for (int t = 0; t < TILES; ++t) {
        const long rbase = rowBase + (long)t * RT;

        // ---- compute: 4 rows x 4 o, dual accumulators ----
        unsigned long long accA[4][4], accB[4][4];
        #pragma unroll
        for (int r = 0; r < 4; ++r)
            #pragma unroll
            for (int oi = 0; oi < 4; ++oi) { accA[r][oi] = 0ULL; accB[r][oi] = 0ULL; }

        #pragma unroll 8
        for (int i = 0; i < 32; ++i) {
            unsigned long long xv[4];
            #pragma unroll
            for (int r = 0; r < 4; ++r) {
                asm volatile("ld.shared.b64 %0, [%1];"
                             : "=l"(xv[r]) : "r"(xb + r * 2048 + i * 64));
            }
            #pragma unroll
            for (int oi = 0; oi < 4; ++oi) {
                ulonglong2 wv = sWu[wslot[oi] + i * 32];   // (wr,wr)|(wi,wi)
                #pragma unroll
                for (int r = 0; r < 4; ++r) {
                    ffma2(accA[r][oi], xv[r], wv.x);
                    ffma2(accB[r][oi], xv[r], wv.y);
                }
            }
        }
        __syncthreads();                 // every warp done reading sX

        // ---- kick off next tile's fill (overlaps the store phase) ----
        if (t + 1 < TILES) {
            const long nb = rbase + RT;
            #pragma unroll
            for (int it = 0; it < 8; ++it) {
                int idx = tid + it * THREADS;
                int k2 = idx & 3, i = (idx >> 2) & 31, row = idx >> 7;
                int s = ((row >> 2) & 3) << 1;
                const float* src = X + (nb + row) * 4096 + i * 128
                                     + (size_t)(kg + k2 * 2) * 2;
                cp_async16(sXbase + row * 2048 + i * 64 + (((2 * k2) ^ s) << 3), src);
            }
            cp_commit();
        }

        // ---- epilogue: merge + direct float2 stores ----
        #pragma unroll
        for (int r = 0; r < 4; ++r) {
            float* op = O + (rbase + row0 + r) * 4096 + (size_t)(kg + kl) * 2;
            #pragma unroll
            for (int oi = 0; oi < 4; ++oi) {
                int o = og + 8 * oi;
                *reinterpret_cast<float2*>(op + (size_t)o * 128) =
                    cmerge(accA[r][oi], accB[r][oi]);
            }
        }

        if (t + 1 < TILES) {
            cp_wait0();
            __syncthreads();
        }
    }
}

extern "C" void kernel_launch(void* const* d_in, const int* in_sizes, int n_in,
                              void* d_out, int out_size)
{
    const float* x = (const float*)d_in[0];   // (8,2048,32,64,2) fp32
    const float* w = (const float*)d_in[1];   // (32,32,64,2) fp32
    float* out = (float*)d_out;               // (8,2048,32,64,2) fp32

    cudaFuncSetAttribute(spectral_r4_kernel,
                         cudaFuncAttributeMaxDynamicSharedMemorySize, SMEM_BYTES);
    dim3 grid(64 / KT, 16384 / (RT * TILES));   // (8, 128); k fastest => L2 x reuse
    spectral_r4_kernel<<<grid, THREADS, SMEM_BYTES>>>(x, w, out);
}

// round 5
// speedup vs baseline: 1.0730x; 1.0530x over previous
#include <cuda_runtime.h>

// SpectralConv1d: out[row,o,k,:] = sum_i complex( x[row,i,k,:] * w[o,i,k,:] )
// rows = 16384, i = o = 32, k = 64, complex = 2 fp32.
//
// Round 5: wavefront-budgeted single-accumulator f32x2 kernel.
//   acc(R,I) += (xr,xi)*(wr,wr) + (-xi,xr)*(wi,wi)
//  - w RAW float2 in smem [k][i][o]                   (64 KB)
//  - x RAW float2 in smem [row][i][kslot] swizzled    (128 KB), cp.async-filled
//  - 16 warps = 8 k x 2 row-halves; lane tile = 8 rows x 4 o, acc = 64 regs
//  - per warp-i: 8 LDS.64 + 2 LDS.128 = 24 wavefronts per 64 FFMA2 (0.375)

#define THREADS 512
#define KT      8                      // k per CTA
#define RT      64                     // rows per tile
#define TILES   2                      // 128 rows per CTA
#define SW_BYTES (KT * 32 * 32 * 8)    // 65536
#define SX_BYTES (RT * 32 * 8 * 8)     // 131072
#define SMEM_BYTES (SW_BYTES + SX_BYTES)  // 196608

__device__ __forceinline__ void ffma2(unsigned long long &d,
                                      unsigned long long a,
                                      unsigned long long b) {
    asm("fma.rn.f32x2 %0, %1, %2, %0;" : "+l"(d) : "l"(a), "l"(b));
}
__device__ __forceinline__ unsigned long long pack2(float lo, float hi) {
    unsigned long long r;
    asm("mov.b64 %0, {%1, %2};" : "=l"(r) : "f"(lo), "f"(hi));
    return r;
}
__device__ __forceinline__ unsigned smem_u32(const void* p) {
    unsigned a;
    asm("{ .reg .u64 t; cvta.to.shared.u64 t, %1; cvt.u32.u64 %0, t; }"
        : "=r"(a) : "l"(p));
    return a;
}
__device__ __forceinline__ void cp_async16(unsigned dst, const void* src) {
    asm volatile("cp.async.ca.shared.global [%0], [%1], 16;\n"
                 :: "r"(dst), "l"(src));
}
__device__ __forceinline__ void cp_commit() {
    asm volatile("cp.async.commit_group;\n");
}
__device__ __forceinline__ void cp_wait0() {
    asm volatile("cp.async.wait_group 0;\n");
}

__global__ void __launch_bounds__(THREADS, 1)
spectral_r5_kernel(const float* __restrict__ X,
                   const float* __restrict__ W,
                   float* __restrict__ O)
{
    extern __shared__ char smem[];
    float2* sW = reinterpret_cast<float2*>(smem);          // [k][i][o] raw
    const unsigned sWbase = smem_u32(smem);
    const unsigned sXbase = smem_u32(smem + SW_BYTES);     // [row][i][kslot]

    const int tid  = threadIdx.x;
    const int lane = tid & 31;
    const int warp = tid >> 5;
    const int kl   = warp & 7;          // warp's local k
    const int half = warp >> 3;         // 32-row half of the 64-row tile
    const int og   = lane & 7;          // o = og*4 + oi
    const int rp   = lane >> 3;         // rows rp*8 .. rp*8+7 within half
    const int kg   = blockIdx.x * KT;
    const long rowBase = (long)blockIdx.y * (RT * TILES);

    // ---- w -> smem RAW float2 [k][i][o] (one time) ----
    #pragma unroll
    for (int it = 0; it < 16; ++it) {
        int idx = tid + it * THREADS;
        int k = idx & 7, i = (idx >> 3) & 31, o = idx >> 8;
        float2 wv = *reinterpret_cast<const float2*>(
            W + (size_t)o * 4096 + i * 128 + (size_t)(kg + k) * 2);
        sW[k * 1024 + i * 32 + o] = wv;
    }

    // ---- x fill via cp.async: [row][i][slot], slot = (2*k2 (+1)) ^ (((row>>3)&3)<<1) ----
    {
        #pragma unroll
        for (int it = 0; it < 16; ++it) {
            int idx = tid + it * THREADS;
            int k2 = idx & 3, i = (idx >> 2) & 31, row = idx >> 7;
            int s = ((row >> 3) & 3) << 1;
            const float* src = X + (rowBase + row) * 4096 + i * 128
                                 + (size_t)(kg + k2 * 2) * 2;
            cp_async16(sXbase + row * 2048 + i * 64 + (((2 * k2) ^ s) << 3), src);
        }
        cp_commit();
    }
    cp_wait0();
    __syncthreads();

    const int row0  = half * 32 + rp * 8;        // lane's first row in tile
    const int xslot = kl ^ (rp << 1);            // constant per lane
    const unsigned xb = sXbase + row0 * 2048 + (xslot << 3);   // + r*2048 + i*64
    const unsigned wb = sWbase + kl * 8192 + og * 32;          // + i*256

    for (int t = 0; t < TILES; ++t) {
        const long rbase = rowBase + (long)t * RT;

        unsigned long long acc[8][4];
        #pragma unroll
        for (int r = 0; r < 8; ++r)
            #pragma unroll
            for (int oi = 0; oi < 4; ++oi) acc[r][oi] = 0ULL;

        #pragma unroll 4
        for (int i = 0; i < 32; ++i) {
            // 4 raw w (wr,wi) via 2 LDS.128, then splat once per i
            float4 w01, w23;
            asm volatile("ld.shared.v4.f32 {%0,%1,%2,%3}, [%4];"
                         : "=f"(w01.x), "=f"(w01.y), "=f"(w01.z), "=f"(w01.w)
                         : "r"(wb + i * 256));
            asm volatile("ld.shared.v4.f32 {%0,%1,%2,%3}, [%4];"
                         : "=f"(w23.x), "=f"(w23.y), "=f"(w23.z), "=f"(w23.w)
                         : "r"(wb + i * 256 + 16));
            unsigned long long wrr[4], wii[4];
            wrr[0] = pack2(w01.x, w01.x);  wii[0] = pack2(w01.y, w01.y);
            wrr[1] = pack2(w01.z, w01.z);  wii[1] = pack2(w01.w, w01.w);
            wrr[2] = pack2(w23.x, w23.x);  wii[2] = pack2(w23.y, w23.y);
            wrr[3] = pack2(w23.z, w23.z);  wii[3] = pack2(w23.w, w23.w);

            #pragma unroll
            for (int r = 0; r < 8; ++r) {
                unsigned long long xv;     // (xr, xi) raw
                asm volatile("ld.shared.b64 %0, [%1];"
                             : "=l"(xv) : "r"(xb + r * 2048 + i * 64));
                float xr, xi;
                asm("mov.b64 {%0,%1}, %2;" : "=f"(xr), "=f"(xi) : "l"(xv));
                unsigned long long xd = pack2(-xi, xr);
                #pragma unroll
                for (int oi = 0; oi < 4; ++oi) {
                    ffma2(acc[r][oi], xv, wrr[oi]);
                    ffma2(acc[r][oi], xd, wii[oi]);
                }
            }
        }
        __syncthreads();              // all warps done reading sX

        // kick next tile's fill; it overlaps the store phase below
        if (t + 1 < TILES) {
            const long nb = rbase + RT;
            #pragma unroll
            for (int it = 0; it < 16; ++it) {
                int idx = tid + it * THREADS;
                int k2 = idx & 3, i = (idx >> 2) & 31, row = idx >> 7;
                int s = ((row >> 3) & 3) << 1;
                const float* src = X + (nb + row) * 4096 + i * 128
                                     + (size_t)(kg + k2 * 2) * 2;
                cp_async16(sXbase + row * 2048 + i * 64 + (((2 * k2) ^ s) << 3), src);
            }
            cp_commit();
        }

        // direct float2 stores; adjacent-k warps fill neighboring 8B in L2
        #pragma unroll
        for (int r = 0; r < 8; ++r) {
            float* op = O + (rbase + row0 + r) * 4096 + (size_t)(kg + kl) * 2;
            #pragma unroll
            for (int oi = 0; oi < 4; ++oi) {
                *reinterpret_cast<float2*>(op + (size_t)(og * 4 + oi) * 128) =
                    *reinterpret_cast<float2*>(&acc[r][oi]);
            }
        }

        if (t + 1 < TILES) {
            cp_wait0();
            __syncthreads();
        }
    }
}

extern "C" void kernel_launch(void* const* d_in, const int* in_sizes, int n_in,
                              void* d_out, int out_size)
{
    const float* x = (const float*)d_in[0];   // (8,2048,32,64,2) fp32
    const float* w = (const float*)d_in[1];   // (32,32,64,2) fp32
    float* out = (float*)d_out;               // (8,2048,32,64,2) fp32

    cudaFuncSetAttribute(spectral_r5_kernel,
                         cudaFuncAttributeMaxDynamicSharedMemorySize, SMEM_BYTES);
    dim3 grid(64 / KT, 16384 / (RT * TILES));   // (8, 128)
    spectral_r5_kernel<<<grid, THREADS, SMEM_BYTES>>>(x, w, out);
}